// round 2
// baseline (speedup 1.0000x reference)
#include <cuda_runtime.h>

#define BB   8
#define NN   2048
#define DIN_ 256
#define DM_  256
#define NH_  4
#define DK_  64
#define ROWS (BB*NN)

// ---------------- scratch (no allocations allowed) ----------------
__device__ float g_q[BB*NH_*NN*DK_];     // [b][h][n][d]
__device__ float g_k[BB*NH_*NN*DK_];
__device__ float g_v[BB*NH_*NN*DK_];
__device__ float g_att[ROWS*DM_];        // [b*n][h*64+d]
__device__ float g_vmean[BB*NH_*DK_];
__device__ int   g_start[BB];
__device__ int   g_end[BB];              // exclusive bound = last-true index

// ---------------- mask scan ----------------
__global__ void mask_scan_kernel(const int* __restrict__ mask) {
    int b = blockIdx.x;
    __shared__ int smin, smax;
    if (threadIdx.x == 0) { smin = NN; smax = -1; }
    __syncthreads();
    int lmin = NN, lmax = -1;
    for (int i = threadIdx.x; i < NN; i += blockDim.x) {
        if (mask[b*NN + i]) { lmin = min(lmin, i); lmax = max(lmax, i); }
    }
    atomicMin(&smin, lmin);
    atomicMax(&smax, lmax);
    __syncthreads();
    if (threadIdx.x == 0) { g_start[b] = smin; g_end[b] = smax; }
}

// ---------------- fused QKV GEMM: [16384,256] x [256,256], head-major output ----------------
__global__ void qkv_gemm_kernel(const float* __restrict__ x,
                                const float* __restrict__ Wq, const float* __restrict__ Wk,
                                const float* __restrict__ Wv,
                                const float* __restrict__ bq, const float* __restrict__ bk,
                                const float* __restrict__ bv)
{
    __shared__ float As[16][65];   // As[k][m], padded vs store conflicts
    __shared__ float Bs[16][64];   // Bs[k][n]
    const float* W; const float* bias; float* dst;
    if (blockIdx.z == 0)      { W = Wq; bias = bq; dst = g_q; }
    else if (blockIdx.z == 1) { W = Wk; bias = bk; dst = g_k; }
    else                      { W = Wv; bias = bv; dst = g_v; }

    const int tid = threadIdx.x;            // 256
    const int m0 = blockIdx.y * 64, n0 = blockIdx.x * 64;
    const int tx = tid & 15, ty = tid >> 4;
    float acc[4][4] = {};

    for (int k0 = 0; k0 < DIN_; k0 += 16) {
        {   // A tile 64x16 -> As[k][m] (transposed)
            int m = tid >> 2, kq = (tid & 3) * 4;
            float4 a = *(const float4*)&x[(size_t)(m0 + m)*DIN_ + k0 + kq];
            As[kq + 0][m] = a.x; As[kq + 1][m] = a.y;
            As[kq + 2][m] = a.z; As[kq + 3][m] = a.w;
        }
        {   // B tile 16x64
            int kq = tid >> 4, nq = (tid & 15) * 4;
            *(float4*)&Bs[kq][nq] = *(const float4*)&W[(size_t)(k0 + kq)*DM_ + n0 + nq];
        }
        __syncthreads();
        #pragma unroll
        for (int kk = 0; kk < 16; kk++) {
            float a[4], bv4[4];
            #pragma unroll
            for (int i = 0; i < 4; i++) a[i] = As[kk][ty*4 + i];
            float4 bb = *(float4*)&Bs[kk][tx*4];
            bv4[0] = bb.x; bv4[1] = bb.y; bv4[2] = bb.z; bv4[3] = bb.w;
            #pragma unroll
            for (int i = 0; i < 4; i++)
                #pragma unroll
                for (int j = 0; j < 4; j++)
                    acc[i][j] += a[i] * bv4[j];
        }
        __syncthreads();
    }

    // epilogue: scatter to head-major [b][h][n][d], d contiguous -> float4 store
    const int gn = n0 + tx*4;           // 4 consecutive cols
    const int h = gn >> 6, d = gn & 63;
    float4 bvv = *(const float4*)&bias[gn];
    #pragma unroll
    for (int i = 0; i < 4; i++) {
        int gm = m0 + ty*4 + i;
        int bIdx = gm >> 11, nIdx = gm & (NN - 1);
        float4 v;
        v.x = acc[i][0] + bvv.x; v.y = acc[i][1] + bvv.y;
        v.z = acc[i][2] + bvv.z; v.w = acc[i][3] + bvv.w;
        *(float4*)&dst[((((size_t)bIdx*NH_ + h)*NN) + nIdx)*DK_ + d] = v;
    }
}

// ---------------- per (b,h) mean of V over all N ----------------
__global__ void vmean_kernel() {
    __shared__ float red[256];
    int bh = blockIdx.x;
    int d = threadIdx.x & 63;
    int seg = threadIdx.x >> 6;
    const float* vptr = g_v + (size_t)bh * NN * DK_;
    float s = 0.f;
    for (int n = seg * (NN/4); n < (seg + 1) * (NN/4); n++)
        s += vptr[(size_t)n*DK_ + d];
    red[threadIdx.x] = s;
    __syncthreads();
    if (seg == 0)
        g_vmean[bh*DK_ + d] = (red[d] + red[64 + d] + red[128 + d] + red[192 + d]) * (1.f/NN);
}

// ---------------- flash attention, 64x64 tiles, fp32 ----------------
#define SST 68   // smem row stride (floats)
__global__ void attn_kernel() {
    extern __shared__ float sm[];
    float* Qs = sm;                    // [64][SST]
    float* Ks = sm + 64*SST;
    float* Vs = sm + 2*64*SST;
    float* Ps = sm + 3*64*SST;

    const int tid = threadIdx.x;       // 256
    const int bh = blockIdx.y, b = bh >> 2, h = bh & 3;
    const int q0 = blockIdx.x * 64;
    const int kstart = g_start[b], kend = g_end[b];
    const float scale = 0.125f;        // 1/sqrt(64)
    const float* qptr = g_q + (size_t)bh * NN * DK_;
    const float* kptr = g_k + (size_t)bh * NN * DK_;
    const float* vptr = g_v + (size_t)bh * NN * DK_;
    const int tx = tid & 15, ty = tid >> 4;
    // thread owns query rows r_i = ty*4+i; S cols c_j = tx+16j; O cols d_j = tx*4+j

    float m[4], l[4], o[4][4];
    #pragma unroll
    for (int i = 0; i < 4; i++) {
        m[i] = -1e30f; l[i] = 0.f;
        #pragma unroll
        for (int j = 0; j < 4; j++) o[i][j] = 0.f;
    }

    const bool anyValid = (q0 < kend) && (q0 + 63 >= kstart);

    if (anyValid) {
        for (int i = tid; i < 64*16; i += 256) {
            int r = i >> 4, c4 = (i & 15) * 4;
            *(float4*)&Qs[r*SST + c4] = *(const float4*)&qptr[(size_t)(q0 + r)*DK_ + c4];
        }
        const int kb0 = kstart & ~63;
        for (int kb = kb0; kb < kend; kb += 64) {
            __syncthreads();   // prev-iter Vs/Ps reads done; Qs ready on first iter
            for (int i = tid; i < 64*16; i += 256) {
                int r = i >> 4, c4 = (i & 15) * 4;
                *(float4*)&Ks[r*SST + c4] = *(const float4*)&kptr[(size_t)(kb + r)*DK_ + c4];
                *(float4*)&Vs[r*SST + c4] = *(const float4*)&vptr[(size_t)(kb + r)*DK_ + c4];
            }
            __syncthreads();

            // S = Q K^T (4x4 microtile per thread)
            float s[4][4];
            #pragma unroll
            for (int i = 0; i < 4; i++)
                #pragma unroll
                for (int j = 0; j < 4; j++) s[i][j] = 0.f;
            #pragma unroll
            for (int k4 = 0; k4 < 16; k4++) {
                float4 qv[4], kv[4];
                #pragma unroll
                for (int i = 0; i < 4; i++) qv[i] = *(float4*)&Qs[(ty*4 + i)*SST + k4*4];
                #pragma unroll
                for (int j = 0; j < 4; j++) kv[j] = *(float4*)&Ks[(tx + 16*j)*SST + k4*4];
                #pragma unroll
                for (int i = 0; i < 4; i++)
                    #pragma unroll
                    for (int j = 0; j < 4; j++)
                        s[i][j] += qv[i].x*kv[j].x + qv[i].y*kv[j].y
                                 + qv[i].z*kv[j].z + qv[i].w*kv[j].w;
            }

            // online softmax per row (16-lane shfl reduction)
            float alpha[4];
            #pragma unroll
            for (int i = 0; i < 4; i++) {
                float mx = -1e30f;
                #pragma unroll
                for (int j = 0; j < 4; j++) {
                    int gk = kb + tx + 16*j;
                    s[i][j] = (gk >= kstart && gk < kend) ? s[i][j]*scale : -1e30f;
                    mx = fmaxf(mx, s[i][j]);
                }
                mx = fmaxf(mx, __shfl_xor_sync(0xffffffffu, mx, 1));
                mx = fmaxf(mx, __shfl_xor_sync(0xffffffffu, mx, 2));
                mx = fmaxf(mx, __shfl_xor_sync(0xffffffffu, mx, 4));
                mx = fmaxf(mx, __shfl_xor_sync(0xffffffffu, mx, 8));
                float mnew = fmaxf(m[i], mx);
                alpha[i] = __expf(m[i] - mnew);
                float ls = 0.f;
                #pragma unroll
                for (int j = 0; j < 4; j++) {
                    float p = __expf(s[i][j] - mnew);
                    Ps[(ty*4 + i)*SST + tx + 16*j] = p;
                    ls += p;
                }
                ls += __shfl_xor_sync(0xffffffffu, ls, 1);
                ls += __shfl_xor_sync(0xffffffffu, ls, 2);
                ls += __shfl_xor_sync(0xffffffffu, ls, 4);
                ls += __shfl_xor_sync(0xffffffffu, ls, 8);
                l[i] = l[i]*alpha[i] + ls;
                m[i] = mnew;
            }
            // Ps rows r_i are written & read by the same half-warp (same ty)
            __syncwarp();

            // O update: o[i][j] (d_j = tx*4+j)
            #pragma unroll
            for (int i = 0; i < 4; i++)
                #pragma unroll
                for (int j = 0; j < 4; j++) o[i][j] *= alpha[i];
            #pragma unroll
            for (int c4 = 0; c4 < 16; c4++) {
                float vr[4][4];
                #pragma unroll
                for (int t = 0; t < 4; t++) {
                    float4 vv = *(float4*)&Vs[(c4*4 + t)*SST + tx*4];
                    vr[t][0] = vv.x; vr[t][1] = vv.y; vr[t][2] = vv.z; vr[t][3] = vv.w;
                }
                #pragma unroll
                for (int i = 0; i < 4; i++) {
                    float4 pv = *(float4*)&Ps[(ty*4 + i)*SST + c4*4];
                    #pragma unroll
                    for (int j = 0; j < 4; j++)
                        o[i][j] += pv.x*vr[0][j] + pv.y*vr[1][j]
                                 + pv.z*vr[2][j] + pv.w*vr[3][j];
                }
            }
        }
    }

    // epilogue: valid rows -> o/l ; invalid rows -> vmean (== uniform softmax)
    float* outp = g_att + (size_t)b*NN*DM_ + h*DK_;
    const float* vm = g_vmean + bh*DK_;
    float4 vmv = *(const float4*)&vm[tx*4];
    #pragma unroll
    for (int i = 0; i < 4; i++) {
        int n = q0 + ty*4 + i;
        bool vrow = (n >= kstart) && (n < kend);
        float4 val;
        if (vrow) {
            float inv = 1.f / l[i];
            val.x = o[i][0]*inv; val.y = o[i][1]*inv;
            val.z = o[i][2]*inv; val.w = o[i][3]*inv;
        } else {
            val = vmv;
        }
        *(float4*)&outp[(size_t)n*DM_ + tx*4] = val;
    }
}

// ---------------- output GEMM: g_att [16384,256] x Wo [256,256] + bo ----------------
__global__ void out_gemm_kernel(const float* __restrict__ Wo,
                                const float* __restrict__ bo,
                                float* __restrict__ out)
{
    __shared__ float As[16][65];
    __shared__ float Bs[16][64];
    const float* A = g_att;
    const int tid = threadIdx.x;
    const int m0 = blockIdx.y * 64, n0 = blockIdx.x * 64;
    const int tx = tid & 15, ty = tid >> 4;
    float acc[4][4] = {};

    for (int k0 = 0; k0 < DM_; k0 += 16) {
        {
            int mm = tid >> 2, kq = (tid & 3) * 4;
            float4 a = *(const float4*)&A[(size_t)(m0 + mm)*DM_ + k0 + kq];
            As[kq + 0][mm] = a.x; As[kq + 1][mm] = a.y;
            As[kq + 2][mm] = a.z; As[kq + 3][mm] = a.w;
        }
        {
            int kq = tid >> 4, nq = (tid & 15) * 4;
            *(float4*)&Bs[kq][nq] = *(const float4*)&Wo[(size_t)(k0 + kq)*DM_ + n0 + nq];
        }
        __syncthreads();
        #pragma unroll
        for (int kk = 0; kk < 16; kk++) {
            float a[4], bv4[4];
            #pragma unroll
            for (int i = 0; i < 4; i++) a[i] = As[kk][ty*4 + i];
            float4 bb = *(float4*)&Bs[kk][tx*4];
            bv4[0] = bb.x; bv4[1] = bb.y; bv4[2] = bb.z; bv4[3] = bb.w;
            #pragma unroll
            for (int i = 0; i < 4; i++)
                #pragma unroll
                for (int j = 0; j < 4; j++)
                    acc[i][j] += a[i] * bv4[j];
        }
        __syncthreads();
    }

    float4 bvv = *(const float4*)&bo[n0 + tx*4];
    #pragma unroll
    for (int i = 0; i < 4; i++) {
        int gm = m0 + ty*4 + i;
        float4 v;
        v.x = acc[i][0] + bvv.x; v.y = acc[i][1] + bvv.y;
        v.z = acc[i][2] + bvv.z; v.w = acc[i][3] + bvv.w;
        *(float4*)&out[(size_t)gm*DM_ + n0 + tx*4] = v;
    }
}

// ---------------- launch ----------------
extern "C" void kernel_launch(void* const* d_in, const int* in_sizes, int n_in,
                              void* d_out, int out_size) {
    const float* x    = (const float*)d_in[0];
    const int*   mask = (const int*)  d_in[1];
    const float* Wq = (const float*)d_in[2]; const float* bq = (const float*)d_in[3];
    const float* Wk = (const float*)d_in[4]; const float* bk = (const float*)d_in[5];
    const float* Wv = (const float*)d_in[6]; const float* bv = (const float*)d_in[7];
    const float* Wo = (const float*)d_in[8]; const float* bo = (const float*)d_in[9];
    float* out = (float*)d_out;

    const int attn_smem = 4 * 64 * SST * (int)sizeof(float);   // 69632 B
    cudaFuncSetAttribute(attn_kernel, cudaFuncAttributeMaxDynamicSharedMemorySize, attn_smem);

    mask_scan_kernel<<<BB, 256>>>(mask);
    qkv_gemm_kernel<<<dim3(DM_/64, ROWS/64, 3), 256>>>(x, Wq, Wk, Wv, bq, bk, bv);
    vmean_kernel<<<BB*NH_, 256>>>();
    attn_kernel<<<dim3(NN/64, BB*NH_), 256, attn_smem>>>();
    out_gemm_kernel<<<dim3(DM_/64, ROWS/64), 256>>>(Wo, bo, out);
}

// round 5
// speedup vs baseline: 2.2175x; 2.2175x over previous
#include <cuda_runtime.h>
#include <cuda_fp16.h>
#include <cstdint>

#define BB   8
#define NN   2048
#define DIN_ 256
#define DM_  256
#define NH_  4
#define DK_  64
#define ROWS (BB*NN)

// ---------------- scratch (no allocations allowed) ----------------
__device__ __half g_qb[BB*NH_*NN*DK_];   // pre-scaled by scale*log2(e)
__device__ __half g_kb[BB*NH_*NN*DK_];
__device__ __half g_vb[BB*NH_*NN*DK_];
__device__ float g_att[ROWS*DM_];        // [b*n][h*64+d]
__device__ float g_vmean[BB*NH_*DK_];
__device__ int   g_start[BB];
__device__ int   g_end[BB];              // exclusive bound = last-true index

#define SCL2E 0.18033688f   /* 0.125 * log2(e) */

// ---------------- small asm helpers ----------------
__device__ __forceinline__ uint32_t smem_u32(const void* p) {
    uint32_t a;
    asm("{ .reg .u64 t; cvta.to.shared.u64 t, %1; cvt.u32.u64 %0, t; }" : "=r"(a) : "l"(p));
    return a;
}
__device__ __forceinline__ float ex2f(float x) {
    float y; asm("ex2.approx.f32 %0, %1;" : "=f"(y) : "f"(x)); return y;
}
#define LDSM_X4(r0,r1,r2,r3,addr) \
    asm volatile("ldmatrix.sync.aligned.m8n8.x4.shared.b16 {%0,%1,%2,%3}, [%4];" \
        : "=r"(r0), "=r"(r1), "=r"(r2), "=r"(r3) : "r"(addr))
#define LDSM_X4_T(r0,r1,r2,r3,addr) \
    asm volatile("ldmatrix.sync.aligned.m8n8.x4.trans.shared.b16 {%0,%1,%2,%3}, [%4];" \
        : "=r"(r0), "=r"(r1), "=r"(r2), "=r"(r3) : "r"(addr))
#define MMA16816(c0,c1,c2,c3,a0,a1,a2,a3,b0,b1) \
    asm volatile("mma.sync.aligned.m16n8k16.row.col.f32.f16.f16.f32 " \
        "{%0,%1,%2,%3}, {%4,%5,%6,%7}, {%8,%9}, {%0,%1,%2,%3};" \
        : "+f"(c0), "+f"(c1), "+f"(c2), "+f"(c3) \
        : "r"(a0), "r"(a1), "r"(a2), "r"(a3), "r"(b0), "r"(b1))

// ---------------- mask scan ----------------
__global__ void mask_scan_kernel(const int* __restrict__ mask) {
    int b = blockIdx.x;
    __shared__ int smin, smax;
    if (threadIdx.x == 0) { smin = NN; smax = -1; }
    __syncthreads();
    int lmin = NN, lmax = -1;
    for (int i = threadIdx.x; i < NN; i += blockDim.x) {
        if (mask[b*NN + i]) { lmin = min(lmin, i); lmax = max(lmax, i); }
    }
    atomicMin(&smin, lmin);
    atomicMax(&smax, lmax);
    __syncthreads();
    if (threadIdx.x == 0) { g_start[b] = smin; g_end[b] = smax; }
}

// ---------------- fused QKV GEMM (fp32 compute, fp16 head-major output) ----------------
__global__ void qkv_gemm_kernel(const float* __restrict__ x,
                                const float* __restrict__ Wq, const float* __restrict__ Wk,
                                const float* __restrict__ Wv,
                                const float* __restrict__ bq, const float* __restrict__ bk,
                                const float* __restrict__ bv)
{
    __shared__ float As[16][65];
    __shared__ float Bs[16][64];
    const float* W; const float* bias; __half* dst; float oscale;
    if (blockIdx.z == 0)      { W = Wq; bias = bq; dst = g_qb; oscale = SCL2E; }
    else if (blockIdx.z == 1) { W = Wk; bias = bk; dst = g_kb; oscale = 1.f; }
    else                      { W = Wv; bias = bv; dst = g_vb; oscale = 1.f; }

    const int tid = threadIdx.x;
    const int m0 = blockIdx.y * 64, n0 = blockIdx.x * 64;
    const int tx = tid & 15, ty = tid >> 4;
    float acc[4][4] = {};

    for (int k0 = 0; k0 < DIN_; k0 += 16) {
        {
            int m = tid >> 2, kq = (tid & 3) * 4;
            float4 a = *(const float4*)&x[(size_t)(m0 + m)*DIN_ + k0 + kq];
            As[kq + 0][m] = a.x; As[kq + 1][m] = a.y;
            As[kq + 2][m] = a.z; As[kq + 3][m] = a.w;
        }
        {
            int kq = tid >> 4, nq = (tid & 15) * 4;
            *(float4*)&Bs[kq][nq] = *(const float4*)&W[(size_t)(k0 + kq)*DM_ + n0 + nq];
        }
        __syncthreads();
        #pragma unroll
        for (int kk = 0; kk < 16; kk++) {
            float a[4], bv4[4];
            #pragma unroll
            for (int i = 0; i < 4; i++) a[i] = As[kk][ty*4 + i];
            float4 bb = *(float4*)&Bs[kk][tx*4];
            bv4[0] = bb.x; bv4[1] = bb.y; bv4[2] = bb.z; bv4[3] = bb.w;
            #pragma unroll
            for (int i = 0; i < 4; i++)
                #pragma unroll
                for (int j = 0; j < 4; j++)
                    acc[i][j] += a[i] * bv4[j];
        }
        __syncthreads();
    }

    const int gn = n0 + tx*4;
    const int h = gn >> 6, d = gn & 63;
    float4 bvv = *(const float4*)&bias[gn];
    #pragma unroll
    for (int i = 0; i < 4; i++) {
        int gm = m0 + ty*4 + i;
        int bIdx = gm >> 11, nIdx = gm & (NN - 1);
        float v0 = (acc[i][0] + bvv.x) * oscale;
        float v1 = (acc[i][1] + bvv.y) * oscale;
        float v2 = (acc[i][2] + bvv.z) * oscale;
        float v3 = (acc[i][3] + bvv.w) * oscale;
        __half2 p0 = __float22half2_rn(make_float2(v0, v1));
        __half2 p1 = __float22half2_rn(make_float2(v2, v3));
        uint2 pk = make_uint2(*(uint32_t*)&p0, *(uint32_t*)&p1);
        *(uint2*)&dst[((((size_t)bIdx*NH_ + h)*NN) + nIdx)*DK_ + d] = pk;
    }
}

// ---------------- per (b,h) mean of V over all N ----------------
__global__ void vmean_kernel() {
    __shared__ float red[256];
    int bh = blockIdx.x;
    int d = threadIdx.x & 63;
    int seg = threadIdx.x >> 6;
    const __half* vptr = g_vb + (size_t)bh * NN * DK_;
    float s = 0.f;
    for (int n = seg * (NN/4); n < (seg + 1) * (NN/4); n++)
        s += __half2float(vptr[(size_t)n*DK_ + d]);
    red[threadIdx.x] = s;
    __syncthreads();
    if (seg == 0)
        g_vmean[bh*DK_ + d] = (red[d] + red[64 + d] + red[128 + d] + red[192 + d]) * (1.f/NN);
}

// ---------------- HMMA fp16 flash attention: 64 q-rows/CTA, 64-key blocks ----------------
#define KST 72    // smem row stride in fp16 (144B rows -> conflict-free ldmatrix)
__global__ void __launch_bounds__(128) attn_mma_kernel() {
    __shared__ __align__(16) __half sQ[64*KST];
    __shared__ __align__(16) __half sK[64*KST];
    __shared__ __align__(16) __half sV[64*KST];

    const int tid = threadIdx.x, lane = tid & 31, warp = tid >> 5;
    const int bh = blockIdx.y, b = bh >> 2, h = bh & 3;
    const int q0 = blockIdx.x * 64;
    const int kstart = g_start[b], kend = g_end[b];
    float* outbase = g_att + ((size_t)b*NN + q0)*DM_ + h*DK_;
    const float* vm = g_vmean + bh*DK_;

    const bool any = (q0 < kend) && (q0 + 63 >= kstart);
    if (!any) {   // whole tile of queries invalid -> uniform softmax == mean(V)
        int r = tid >> 1, c0 = (tid & 1) * 32;
        #pragma unroll
        for (int j = 0; j < 8; j++)
            *(float4*)&outbase[(size_t)r*DM_ + c0 + j*4] = *(const float4*)&vm[c0 + j*4];
        return;
    }

    const __half* qp = g_qb + ((size_t)bh*NN + q0)*DK_;
    const __half* kp = g_kb + (size_t)bh*NN*DK_;
    const __half* vp = g_vb + (size_t)bh*NN*DK_;

    // ---- load Q tile (fp16, already pre-scaled) ----
    for (int i = tid; i < 512; i += 128) {
        int r = i >> 3, j = i & 7;
        *(uint4*)&sQ[r*KST + j*8] = *(const uint4*)&qp[r*DK_ + j*8];
    }
    __syncthreads();

    // ---- Q fragments (held in regs for all key blocks) ----
    uint32_t qa[4][4];
    {
        uint32_t qaddr = smem_u32(sQ) + (uint32_t)(((warp*16 + (lane & 15))*KST + (lane >> 4)*8) * 2);
        #pragma unroll
        for (int ks = 0; ks < 4; ks++)
            LDSM_X4(qa[ks][0], qa[ks][1], qa[ks][2], qa[ks][3], qaddr + ks*32);
    }

    const uint32_t kfbase = smem_u32(sK) +
        (uint32_t)(((((lane & 7) + ((lane >> 4) << 3))*KST) + ((lane >> 3) & 1)*8) * 2);
    const uint32_t vfbase = smem_u32(sV) +
        (uint32_t)(((((lane & 7) + (((lane >> 3) & 1) << 3))*KST) + (lane >> 4)*8) * 2);

    float oacc[32];
    #pragma unroll
    for (int i = 0; i < 32; i++) oacc[i] = 0.f;
    float l_lo = 0.f, l_hi = 0.f;

    const int kb0 = kstart & ~63;
    for (int kb = kb0; kb < kend; kb += 64) {
        __syncthreads();   // prior-iteration smem reads done
        for (int i = tid; i < 512; i += 128) {
            int r = i >> 3, j = i & 7;
            int gr = kb + r; if (gr > NN - 1) gr = NN - 1;
            *(uint4*)&sK[r*KST + j*8] = *(const uint4*)&kp[(size_t)gr*DK_ + j*8];
            *(uint4*)&sV[r*KST + j*8] = *(const uint4*)&vp[(size_t)gr*DK_ + j*8];
        }
        __syncthreads();

        // ---- S = Q K^T : 16x64 per warp, accum fp32 (log2-domain, pre-scaled) ----
        float sacc[32];
        #pragma unroll
        for (int i = 0; i < 32; i++) sacc[i] = 0.f;
        #pragma unroll
        for (int ks = 0; ks < 4; ks++) {
            #pragma unroll
            for (int ntp = 0; ntp < 4; ntp++) {
                uint32_t b0, b1, b2, b3;
                LDSM_X4(b0, b1, b2, b3, kfbase + (uint32_t)((ntp*16*KST + ks*16) * 2));
                MMA16816(sacc[(2*ntp)*4+0], sacc[(2*ntp)*4+1], sacc[(2*ntp)*4+2], sacc[(2*ntp)*4+3],
                         qa[ks][0], qa[ks][1], qa[ks][2], qa[ks][3], b0, b1);
                MMA16816(sacc[(2*ntp+1)*4+0], sacc[(2*ntp+1)*4+1], sacc[(2*ntp+1)*4+2], sacc[(2*ntp+1)*4+3],
                         qa[ks][0], qa[ks][1], qa[ks][2], qa[ks][3], b2, b3);
            }
        }

        // ---- softmax (no max subtraction: logits bounded) ----
        const bool partial = (kb < kstart) || (kb + 64 > kend);
        uint32_t ppack[16];
        float ls_lo = 0.f, ls_hi = 0.f;
        #pragma unroll
        for (int j = 0; j < 8; j++) {
            float c0 = sacc[4*j+0], c1 = sacc[4*j+1], c2 = sacc[4*j+2], c3 = sacc[4*j+3];
            float p0, p1, p2, p3;
            if (partial) {
                int col = kb + j*8 + (lane & 3)*2;
                bool v0 = (col >= kstart) & (col < kend);
                bool v1 = (col + 1 >= kstart) & (col + 1 < kend);
                p0 = v0 ? ex2f(c0) : 0.f;
                p1 = v1 ? ex2f(c1) : 0.f;
                p2 = v0 ? ex2f(c2) : 0.f;
                p3 = v1 ? ex2f(c3) : 0.f;
            } else {
                p0 = ex2f(c0); p1 = ex2f(c1); p2 = ex2f(c2); p3 = ex2f(c3);
            }
            __half2 q0p = __float22half2_rn(make_float2(p0, p1));
            __half2 q1p = __float22half2_rn(make_float2(p2, p3));
            ppack[2*j]   = *(uint32_t*)&q0p;
            ppack[2*j+1] = *(uint32_t*)&q1p;
            // denominator from the ROUNDED p so numerator/denominator weights match
            float2 f0 = __half22float2(q0p);
            float2 f1 = __half22float2(q1p);
            ls_lo += f0.x + f0.y;
            ls_hi += f1.x + f1.y;
        }
        ls_lo += __shfl_xor_sync(0xffffffffu, ls_lo, 1);
        ls_lo += __shfl_xor_sync(0xffffffffu, ls_lo, 2);
        ls_hi += __shfl_xor_sync(0xffffffffu, ls_hi, 1);
        ls_hi += __shfl_xor_sync(0xffffffffu, ls_hi, 2);
        l_lo += ls_lo;
        l_hi += ls_hi;

        // ---- O += P V : P (A-frag) direct from S accum layout ----
        #pragma unroll
        for (int kk = 0; kk < 4; kk++) {
            #pragma unroll
            for (int dt = 0; dt < 4; dt++) {
                uint32_t b0, b1, b2, b3;
                LDSM_X4_T(b0, b1, b2, b3, vfbase + (uint32_t)((kk*16*KST + dt*16) * 2));
                MMA16816(oacc[(2*dt)*4+0], oacc[(2*dt)*4+1], oacc[(2*dt)*4+2], oacc[(2*dt)*4+3],
                         ppack[4*kk+0], ppack[4*kk+1], ppack[4*kk+2], ppack[4*kk+3], b0, b1);
                MMA16816(oacc[(2*dt+1)*4+0], oacc[(2*dt+1)*4+1], oacc[(2*dt+1)*4+2], oacc[(2*dt+1)*4+3],
                         ppack[4*kk+0], ppack[4*kk+1], ppack[4*kk+2], ppack[4*kk+3], b2, b3);
            }
        }
    }

    // ---- epilogue ----
    const int r_lo = q0 + warp*16 + (lane >> 2);
    const int r_hi = r_lo + 8;
    const bool v_lo = (r_lo >= kstart) && (r_lo < kend);
    const bool v_hi = (r_hi >= kstart) && (r_hi < kend);
    const float inv_lo = v_lo ? 1.f / l_lo : 0.f;
    const float inv_hi = v_hi ? 1.f / l_hi : 0.f;
    float* orow_lo = g_att + ((size_t)b*NN + r_lo)*DM_ + h*DK_;
    float* orow_hi = g_att + ((size_t)b*NN + r_hi)*DM_ + h*DK_;
    #pragma unroll
    for (int j = 0; j < 8; j++) {
        int d = j*8 + (lane & 3)*2;
        float2 lo, hi;
        if (v_lo) { lo.x = oacc[4*j+0]*inv_lo; lo.y = oacc[4*j+1]*inv_lo; }
        else      { lo.x = vm[d]; lo.y = vm[d+1]; }
        if (v_hi) { hi.x = oacc[4*j+2]*inv_hi; hi.y = oacc[4*j+3]*inv_hi; }
        else      { hi.x = vm[d]; hi.y = vm[d+1]; }
        *(float2*)&orow_lo[d] = lo;
        *(float2*)&orow_hi[d] = hi;
    }
}

// ---------------- output GEMM: g_att [16384,256] x Wo [256,256] + bo ----------------
__global__ void out_gemm_kernel(const float* __restrict__ Wo,
                                const float* __restrict__ bo,
                                float* __restrict__ out)
{
    __shared__ float As[16][65];
    __shared__ float Bs[16][64];
    const float* A = g_att;
    const int tid = threadIdx.x;
    const int m0 = blockIdx.y * 64, n0 = blockIdx.x * 64;
    const int tx = tid & 15, ty = tid >> 4;
    float acc[4][4] = {};

    for (int k0 = 0; k0 < DM_; k0 += 16) {
        {
            int mm = tid >> 2, kq = (tid & 3) * 4;
            float4 a = *(const float4*)&A[(size_t)(m0 + mm)*DM_ + k0 + kq];
            As[kq + 0][mm] = a.x; As[kq + 1][mm] = a.y;
            As[kq + 2][mm] = a.z; As[kq + 3][mm] = a.w;
        }
        {
            int kq = tid >> 4, nq = (tid & 15) * 4;
            *(float4*)&Bs[kq][nq] = *(const float4*)&Wo[(size_t)(k0 + kq)*DM_ + n0 + nq];
        }
        __syncthreads();
        #pragma unroll
        for (int kk = 0; kk < 16; kk++) {
            float a[4], bv4[4];
            #pragma unroll
            for (int i = 0; i < 4; i++) a[i] = As[kk][ty*4 + i];
            float4 bb = *(float4*)&Bs[kk][tx*4];
            bv4[0] = bb.x; bv4[1] = bb.y; bv4[2] = bb.z; bv4[3] = bb.w;
            #pragma unroll
            for (int i = 0; i < 4; i++)
                #pragma unroll
                for (int j = 0; j < 4; j++)
                    acc[i][j] += a[i] * bv4[j];
        }
        __syncthreads();
    }

    float4 bvv = *(const float4*)&bo[n0 + tx*4];
    #pragma unroll
    for (int i = 0; i < 4; i++) {
        int gm = m0 + ty*4 + i;
        float4 v;
        v.x = acc[i][0] + bvv.x; v.y = acc[i][1] + bvv.y;
        v.z = acc[i][2] + bvv.z; v.w = acc[i][3] + bvv.w;
        *(float4*)&out[(size_t)gm*DM_ + n0 + tx*4] = v;
    }
}

// ---------------- launch ----------------
extern "C" void kernel_launch(void* const* d_in, const int* in_sizes, int n_in,
                              void* d_out, int out_size) {
    const float* x    = (const float*)d_in[0];
    const int*   mask = (const int*)  d_in[1];
    const float* Wq = (const float*)d_in[2]; const float* bq = (const float*)d_in[3];
    const float* Wk = (const float*)d_in[4]; const float* bk = (const float*)d_in[5];
    const float* Wv = (const float*)d_in[6]; const float* bv = (const float*)d_in[7];
    const float* Wo = (const float*)d_in[8]; const float* bo = (const float*)d_in[9];
    float* out = (float*)d_out;

    mask_scan_kernel<<<BB, 256>>>(mask);
    qkv_gemm_kernel<<<dim3(DM_/64, ROWS/64, 3), 256>>>(x, Wq, Wk, Wv, bq, bk, bv);
    vmean_kernel<<<BB*NH_, 256>>>();
    attn_mma_kernel<<<dim3(NN/64, BB*NH_), 128>>>();
    out_gemm_kernel<<<dim3(DM_/64, ROWS/64), 256>>>(Wo, bo, out);
}

// round 6
// speedup vs baseline: 3.8787x; 1.7492x over previous
#include <cuda_runtime.h>
#include <cuda_fp16.h>
#include <cstdint>

#define BB   8
#define NN   2048
#define DIN_ 256
#define DM_  256
#define NH_  4
#define DK_  64
#define ROWS (BB*NN)

// ---------------- scratch (no allocations allowed) ----------------
__device__ __half g_qb[BB*NH_*NN*DK_];   // pre-scaled by scale*log2(e)
__device__ __half g_kb[BB*NH_*NN*DK_];
__device__ __half g_vb[BB*NH_*NN*DK_];
__device__ __half g_wt[3*DM_*DIN_];      // W^T [z][n][k], fp16
__device__ float g_att[ROWS*DM_];        // [b*n][h*64+d]
__device__ float g_vmean[BB*NH_*DK_];
__device__ int   g_start[BB];
__device__ int   g_end[BB];              // exclusive bound = last-true index

#define SCL2E 0.18033688f   /* 0.125 * log2(e) */

// ---------------- small asm helpers ----------------
__device__ __forceinline__ uint32_t smem_u32(const void* p) {
    uint32_t a;
    asm("{ .reg .u64 t; cvta.to.shared.u64 t, %1; cvt.u32.u64 %0, t; }" : "=r"(a) : "l"(p));
    return a;
}
__device__ __forceinline__ float ex2f(float x) {
    float y; asm("ex2.approx.f32 %0, %1;" : "=f"(y) : "f"(x)); return y;
}
#define LDSM_X4(r0,r1,r2,r3,addr) \
    asm volatile("ldmatrix.sync.aligned.m8n8.x4.shared.b16 {%0,%1,%2,%3}, [%4];" \
        : "=r"(r0), "=r"(r1), "=r"(r2), "=r"(r3) : "r"(addr))
#define LDSM_X4_T(r0,r1,r2,r3,addr) \
    asm volatile("ldmatrix.sync.aligned.m8n8.x4.trans.shared.b16 {%0,%1,%2,%3}, [%4];" \
        : "=r"(r0), "=r"(r1), "=r"(r2), "=r"(r3) : "r"(addr))
#define MMA16816(c0,c1,c2,c3,a0,a1,a2,a3,b0,b1) \
    asm volatile("mma.sync.aligned.m16n8k16.row.col.f32.f16.f16.f32 " \
        "{%0,%1,%2,%3}, {%4,%5,%6,%7}, {%8,%9}, {%0,%1,%2,%3};" \
        : "+f"(c0), "+f"(c1), "+f"(c2), "+f"(c3) \
        : "r"(a0), "r"(a1), "r"(a2), "r"(a3), "r"(b0), "r"(b1))
#define CP_ASYNC16(smem, gptr) \
    asm volatile("cp.async.cg.shared.global [%0], [%1], 16;" :: "r"(smem), "l"(gptr))
#define CP_COMMIT() asm volatile("cp.async.commit_group;" ::: "memory")
#define CP_WAIT(n)  asm volatile("cp.async.wait_group %0;" :: "n"(n) : "memory")

// ---------------- mask scan ----------------
__global__ void mask_scan_kernel(const int* __restrict__ mask) {
    int b = blockIdx.x;
    __shared__ int smin, smax;
    if (threadIdx.x == 0) { smin = NN; smax = -1; }
    __syncthreads();
    int lmin = NN, lmax = -1;
    for (int i = threadIdx.x; i < NN; i += blockDim.x) {
        if (mask[b*NN + i]) { lmin = min(lmin, i); lmax = max(lmax, i); }
    }
    atomicMin(&smin, lmin);
    atomicMax(&smax, lmax);
    __syncthreads();
    if (threadIdx.x == 0) { g_start[b] = smin; g_end[b] = smax; }
}

// ---------------- weight transpose+convert: g_wt[z][n][k] = fp16(W[k][n]) ----------------
__global__ void cvt_w_kernel(const float* __restrict__ Wq, const float* __restrict__ Wk,
                             const float* __restrict__ Wv) {
    __shared__ float t[32][33];
    const float* W = blockIdx.z == 0 ? Wq : blockIdx.z == 1 ? Wk : Wv;
    __half* wt = g_wt + blockIdx.z * (DM_*DIN_);
    int n0 = blockIdx.x * 32, k0 = blockIdx.y * 32;
    for (int i = threadIdx.y; i < 32; i += 8)
        t[i][threadIdx.x] = W[(size_t)(k0 + i)*DM_ + n0 + threadIdx.x];
    __syncthreads();
    for (int i = threadIdx.y; i < 32; i += 8)
        wt[(size_t)(n0 + i)*DIN_ + k0 + threadIdx.x] = __float2half_rn(t[threadIdx.x][i]);
}

// ---------------- fused QKV GEMM, fp16 HMMA (same fragment layout as attention) ----------------
#define GST 72
__global__ void __launch_bounds__(128) qkv_hmma_kernel(const float* __restrict__ x,
                                                       const float* __restrict__ bq,
                                                       const float* __restrict__ bk,
                                                       const float* __restrict__ bv)
{
    __shared__ __align__(16) __half sA[64*GST];
    __shared__ __align__(16) __half sB[64*GST];

    const int tid = threadIdx.x, lane = tid & 31, warp = tid >> 5;
    const int z = blockIdx.z;
    const int m0 = blockIdx.y * 64;
    const int h  = blockIdx.x;                 // 64-col tile == head
    const __half* wt = g_wt + (size_t)z * (DM_*DIN_);
    const float* bias = z == 0 ? bq : z == 1 ? bk : bv;
    __half* dst = z == 0 ? g_qb : z == 1 ? g_kb : g_vb;
    const float os = z == 0 ? SCL2E : 1.f;

    const uint32_t afb = smem_u32(sA) +
        (uint32_t)(((warp*16 + (lane & 15))*GST + (lane >> 4)*8) * 2);
    const uint32_t bfb = smem_u32(sB) +
        (uint32_t)(((((lane & 7) + ((lane >> 4) << 3))*GST) + ((lane >> 3) & 1)*8) * 2);

    float acc[32];
    #pragma unroll
    for (int i = 0; i < 32; i++) acc[i] = 0.f;

    for (int k0 = 0; k0 < DIN_; k0 += 64) {
        __syncthreads();
        for (int i = tid; i < 512; i += 128) {
            int r = i >> 3, j = i & 7;
            // A: x rows (fp32 -> fp16)
            float4 a0 = *(const float4*)&x[(size_t)(m0 + r)*DIN_ + k0 + j*8];
            float4 a1 = *(const float4*)&x[(size_t)(m0 + r)*DIN_ + k0 + j*8 + 4];
            __half2 h0 = __float22half2_rn(make_float2(a0.x, a0.y));
            __half2 h1 = __float22half2_rn(make_float2(a0.z, a0.w));
            __half2 h2 = __float22half2_rn(make_float2(a1.x, a1.y));
            __half2 h3 = __float22half2_rn(make_float2(a1.z, a1.w));
            uint4 pk = make_uint4(*(uint32_t*)&h0, *(uint32_t*)&h1,
                                  *(uint32_t*)&h2, *(uint32_t*)&h3);
            *(uint4*)&sA[r*GST + j*8] = pk;
            // B: W^T rows (n-major, k contiguous), already fp16
            *(uint4*)&sB[r*GST + j*8] = *(const uint4*)&wt[(size_t)(h*64 + r)*DIN_ + k0 + j*8];
        }
        __syncthreads();

        uint32_t af[4][4];
        #pragma unroll
        for (int ks = 0; ks < 4; ks++)
            LDSM_X4(af[ks][0], af[ks][1], af[ks][2], af[ks][3], afb + ks*32);

        #pragma unroll
        for (int ks = 0; ks < 4; ks++) {
            #pragma unroll
            for (int ntp = 0; ntp < 4; ntp++) {
                uint32_t b0, b1, b2, b3;
                LDSM_X4(b0, b1, b2, b3, bfb + (uint32_t)((ntp*16*GST + ks*16) * 2));
                MMA16816(acc[(2*ntp)*4+0], acc[(2*ntp)*4+1], acc[(2*ntp)*4+2], acc[(2*ntp)*4+3],
                         af[ks][0], af[ks][1], af[ks][2], af[ks][3], b0, b1);
                MMA16816(acc[(2*ntp+1)*4+0], acc[(2*ntp+1)*4+1], acc[(2*ntp+1)*4+2], acc[(2*ntp+1)*4+3],
                         af[ks][0], af[ks][1], af[ks][2], af[ks][3], b2, b3);
            }
        }
    }

    // epilogue: rows r_lo/r_hi, cols j*8 + (lane&3)*2 -> head-major fp16
    const int r_lo = m0 + warp*16 + (lane >> 2);
    const int r_hi = r_lo + 8;
    const int b_lo = r_lo >> 11, n_lo = r_lo & (NN - 1);
    const int b_hi = r_hi >> 11, n_hi = r_hi & (NN - 1);
    __half* p_lo = dst + ((((size_t)b_lo*NH_ + h)*NN) + n_lo)*DK_;
    __half* p_hi = dst + ((((size_t)b_hi*NH_ + h)*NN) + n_hi)*DK_;
    #pragma unroll
    for (int j = 0; j < 8; j++) {
        int d = j*8 + (lane & 3)*2;
        float2 bv2 = *(const float2*)&bias[h*64 + d];
        __half2 lo = __float22half2_rn(make_float2((acc[4*j+0] + bv2.x)*os,
                                                   (acc[4*j+1] + bv2.y)*os));
        __half2 hi = __float22half2_rn(make_float2((acc[4*j+2] + bv2.x)*os,
                                                   (acc[4*j+3] + bv2.y)*os));
        *(uint32_t*)&p_lo[d] = *(uint32_t*)&lo;
        *(uint32_t*)&p_hi[d] = *(uint32_t*)&hi;
    }
}

// ---------------- per (b,h) mean of V over all N ----------------
__global__ void vmean_kernel() {
    __shared__ float red[256];
    int bh = blockIdx.x;
    int d = threadIdx.x & 63;
    int seg = threadIdx.x >> 6;
    const __half* vptr = g_vb + (size_t)bh * NN * DK_;
    float s = 0.f;
    for (int n = seg * (NN/4); n < (seg + 1) * (NN/4); n++)
        s += __half2float(vptr[(size_t)n*DK_ + d]);
    red[threadIdx.x] = s;
    __syncthreads();
    if (seg == 0)
        g_vmean[bh*DK_ + d] = (red[d] + red[64 + d] + red[128 + d] + red[192 + d]) * (1.f/NN);
}

// ---------------- HMMA fp16 flash attention + cp.async 2-stage pipeline ----------------
#define KST 72    // smem row stride in fp16 (144B rows -> conflict-free ldmatrix)
#define STB ((uint32_t)(64*KST*2))   // stage bytes

__device__ __forceinline__ void attn_prefetch(uint32_t skb, uint32_t svb,
                                              const __half* kp, const __half* vp,
                                              int kb, int tid) {
    #pragma unroll
    for (int u = 0; u < 4; u++) {
        int i = tid + u*128;
        int r = i >> 3, j = i & 7;
        int gr = kb + r; if (gr > NN - 1) gr = NN - 1;
        uint32_t so = (uint32_t)((r*KST + j*8) * 2);
        CP_ASYNC16(skb + so, kp + (size_t)gr*DK_ + j*8);
        CP_ASYNC16(svb + so, vp + (size_t)gr*DK_ + j*8);
    }
}

__global__ void __launch_bounds__(128) attn_mma_kernel() {
    __shared__ __align__(16) __half sQ[64*KST];
    __shared__ __align__(16) __half sK[2][64*KST];
    __shared__ __align__(16) __half sV[2][64*KST];

    const int tid = threadIdx.x, lane = tid & 31, warp = tid >> 5;
    const int bh = blockIdx.y, b = bh >> 2, h = bh & 3;
    const int q0 = blockIdx.x * 64;
    const int kstart = g_start[b], kend = g_end[b];
    float* outbase = g_att + ((size_t)b*NN + q0)*DM_ + h*DK_;
    const float* vm = g_vmean + bh*DK_;

    const bool any = (q0 < kend) && (q0 + 63 >= kstart);
    if (!any) {   // whole tile of queries invalid -> uniform softmax == mean(V)
        int r = tid >> 1, c0 = (tid & 1) * 32;
        #pragma unroll
        for (int j = 0; j < 8; j++)
            *(float4*)&outbase[(size_t)r*DM_ + c0 + j*4] = *(const float4*)&vm[c0 + j*4];
        return;
    }

    const __half* qp = g_qb + ((size_t)bh*NN + q0)*DK_;
    const __half* kp = g_kb + (size_t)bh*NN*DK_;
    const __half* vp = g_vb + (size_t)bh*NN*DK_;

    const uint32_t skb0 = smem_u32(sK), svb0 = smem_u32(sV);
    const int kb0 = kstart & ~63;

    // prefetch stage 0 while we stage Q
    attn_prefetch(skb0, svb0, kp, vp, kb0, tid);
    CP_COMMIT();

    for (int i = tid; i < 512; i += 128) {
        int r = i >> 3, j = i & 7;
        *(uint4*)&sQ[r*KST + j*8] = *(const uint4*)&qp[r*DK_ + j*8];
    }
    __syncthreads();

    uint32_t qa[4][4];
    {
        uint32_t qaddr = smem_u32(sQ) + (uint32_t)(((warp*16 + (lane & 15))*KST + (lane >> 4)*8) * 2);
        #pragma unroll
        for (int ks = 0; ks < 4; ks++)
            LDSM_X4(qa[ks][0], qa[ks][1], qa[ks][2], qa[ks][3], qaddr + ks*32);
    }

    const uint32_t kfo = (uint32_t)(((((lane & 7) + ((lane >> 4) << 3))*KST) + ((lane >> 3) & 1)*8) * 2);
    const uint32_t vfo = (uint32_t)(((((lane & 7) + (((lane >> 3) & 1) << 3))*KST) + (lane >> 4)*8) * 2);

    float oacc[32];
    #pragma unroll
    for (int i = 0; i < 32; i++) oacc[i] = 0.f;
    float l_lo = 0.f, l_hi = 0.f;
    int st = 0;

    for (int kb = kb0; kb < kend; kb += 64) {
        const bool nxt = (kb + 64) < kend;
        if (nxt) {
            attn_prefetch(skb0 + (st^1)*STB, svb0 + (st^1)*STB, kp, vp, kb + 64, tid);
            CP_COMMIT();
            CP_WAIT(1);          // current stage arrived; prefetch may be in flight
        } else {
            CP_WAIT(0);
        }
        __syncthreads();

        const uint32_t kfbase = skb0 + st*STB + kfo;
        const uint32_t vfbase = svb0 + st*STB + vfo;

        // ---- S = Q K^T : 16x64 per warp, accum fp32 (log2-domain, pre-scaled) ----
        float sacc[32];
        #pragma unroll
        for (int i = 0; i < 32; i++) sacc[i] = 0.f;
        #pragma unroll
        for (int ks = 0; ks < 4; ks++) {
            #pragma unroll
            for (int ntp = 0; ntp < 4; ntp++) {
                uint32_t b0, b1, b2, b3;
                LDSM_X4(b0, b1, b2, b3, kfbase + (uint32_t)((ntp*16*KST + ks*16) * 2));
                MMA16816(sacc[(2*ntp)*4+0], sacc[(2*ntp)*4+1], sacc[(2*ntp)*4+2], sacc[(2*ntp)*4+3],
                         qa[ks][0], qa[ks][1], qa[ks][2], qa[ks][3], b0, b1);
                MMA16816(sacc[(2*ntp+1)*4+0], sacc[(2*ntp+1)*4+1], sacc[(2*ntp+1)*4+2], sacc[(2*ntp+1)*4+3],
                         qa[ks][0], qa[ks][1], qa[ks][2], qa[ks][3], b2, b3);
            }
        }

        // ---- softmax (no max subtraction: logits bounded) ----
        const bool partial = (kb < kstart) || (kb + 64 > kend);
        uint32_t ppack[16];
        float ls_lo = 0.f, ls_hi = 0.f;
        #pragma unroll
        for (int j = 0; j < 8; j++) {
            float c0 = sacc[4*j+0], c1 = sacc[4*j+1], c2 = sacc[4*j+2], c3 = sacc[4*j+3];
            float p0, p1, p2, p3;
            if (partial) {
                int col = kb + j*8 + (lane & 3)*2;
                bool v0 = (col >= kstart) & (col < kend);
                bool v1 = (col + 1 >= kstart) & (col + 1 < kend);
                p0 = v0 ? ex2f(c0) : 0.f;
                p1 = v1 ? ex2f(c1) : 0.f;
                p2 = v0 ? ex2f(c2) : 0.f;
                p3 = v1 ? ex2f(c3) : 0.f;
            } else {
                p0 = ex2f(c0); p1 = ex2f(c1); p2 = ex2f(c2); p3 = ex2f(c3);
            }
            __half2 q0p = __float22half2_rn(make_float2(p0, p1));
            __half2 q1p = __float22half2_rn(make_float2(p2, p3));
            ppack[2*j]   = *(uint32_t*)&q0p;
            ppack[2*j+1] = *(uint32_t*)&q1p;
            // denominator from the ROUNDED p so numerator/denominator weights match
            float2 f0 = __half22float2(q0p);
            float2 f1 = __half22float2(q1p);
            ls_lo += f0.x + f0.y;
            ls_hi += f1.x + f1.y;
        }
        ls_lo += __shfl_xor_sync(0xffffffffu, ls_lo, 1);
        ls_lo += __shfl_xor_sync(0xffffffffu, ls_lo, 2);
        ls_hi += __shfl_xor_sync(0xffffffffu, ls_hi, 1);
        ls_hi += __shfl_xor_sync(0xffffffffu, ls_hi, 2);
        l_lo += ls_lo;
        l_hi += ls_hi;

        // ---- O += P V : P (A-frag) direct from S accum layout ----
        #pragma unroll
        for (int kk = 0; kk < 4; kk++) {
            #pragma unroll
            for (int dt = 0; dt < 4; dt++) {
                uint32_t b0, b1, b2, b3;
                LDSM_X4_T(b0, b1, b2, b3, vfbase + (uint32_t)((kk*16*KST + dt*16) * 2));
                MMA16816(oacc[(2*dt)*4+0], oacc[(2*dt)*4+1], oacc[(2*dt)*4+2], oacc[(2*dt)*4+3],
                         ppack[4*kk+0], ppack[4*kk+1], ppack[4*kk+2], ppack[4*kk+3], b0, b1);
                MMA16816(oacc[(2*dt+1)*4+0], oacc[(2*dt+1)*4+1], oacc[(2*dt+1)*4+2], oacc[(2*dt+1)*4+3],
                         ppack[4*kk+0], ppack[4*kk+1], ppack[4*kk+2], ppack[4*kk+3], b2, b3);
            }
        }
        __syncthreads();   // all reads of stage st done before next-iter prefetch overwrites it
        st ^= 1;
    }

    // ---- epilogue ----
    const int r_lo = q0 + warp*16 + (lane >> 2);
    const int r_hi = r_lo + 8;
    const bool v_lo = (r_lo >= kstart) && (r_lo < kend);
    const bool v_hi = (r_hi >= kstart) && (r_hi < kend);
    const float inv_lo = v_lo ? 1.f / l_lo : 0.f;
    const float inv_hi = v_hi ? 1.f / l_hi : 0.f;
    float* orow_lo = g_att + ((size_t)b*NN + r_lo)*DM_ + h*DK_;
    float* orow_hi = g_att + ((size_t)b*NN + r_hi)*DM_ + h*DK_;
    #pragma unroll
    for (int j = 0; j < 8; j++) {
        int d = j*8 + (lane & 3)*2;
        float2 lo, hi;
        if (v_lo) { lo.x = oacc[4*j+0]*inv_lo; lo.y = oacc[4*j+1]*inv_lo; }
        else      { lo.x = vm[d]; lo.y = vm[d+1]; }
        if (v_hi) { hi.x = oacc[4*j+2]*inv_hi; hi.y = oacc[4*j+3]*inv_hi; }
        else      { hi.x = vm[d]; hi.y = vm[d+1]; }
        *(float2*)&orow_lo[d] = lo;
        *(float2*)&orow_hi[d] = hi;
    }
}

// ---------------- output GEMM: g_att [16384,256] x Wo [256,256] + bo ----------------
__global__ void out_gemm_kernel(const float* __restrict__ Wo,
                                const float* __restrict__ bo,
                                float* __restrict__ out)
{
    __shared__ float As[16][65];
    __shared__ float Bs[16][64];
    const float* A = g_att;
    const int tid = threadIdx.x;
    const int m0 = blockIdx.y * 64, n0 = blockIdx.x * 64;
    const int tx = tid & 15, ty = tid >> 4;
    float acc[4][4] = {};

    for (int k0 = 0; k0 < DM_; k0 += 16) {
        {
            int mm = tid >> 2, kq = (tid & 3) * 4;
            float4 a = *(const float4*)&A[(size_t)(m0 + mm)*DM_ + k0 + kq];
            As[kq + 0][mm] = a.x; As[kq + 1][mm] = a.y;
            As[kq + 2][mm] = a.z; As[kq + 3][mm] = a.w;
        }
        {
            int kq = tid >> 4, nq = (tid & 15) * 4;
            *(float4*)&Bs[kq][nq] = *(const float4*)&Wo[(size_t)(k0 + kq)*DM_ + n0 + nq];
        }
        __syncthreads();
        #pragma unroll
        for (int kk = 0; kk < 16; kk++) {
            float a[4], bv4[4];
            #pragma unroll
            for (int i = 0; i < 4; i++) a[i] = As[kk][ty*4 + i];
            float4 bb = *(float4*)&Bs[kk][tx*4];
            bv4[0] = bb.x; bv4[1] = bb.y; bv4[2] = bb.z; bv4[3] = bb.w;
            #pragma unroll
            for (int i = 0; i < 4; i++)
                #pragma unroll
                for (int j = 0; j < 4; j++)
                    acc[i][j] += a[i] * bv4[j];
        }
        __syncthreads();
    }

    float4 bvv = *(const float4*)&bo[n0 + tx*4];
    #pragma unroll
    for (int i = 0; i < 4; i++) {
        int gm = m0 + ty*4 + i;
        float4 v;
        v.x = acc[i][0] + bvv.x; v.y = acc[i][1] + bvv.y;
        v.z = acc[i][2] + bvv.z; v.w = acc[i][3] + bvv.w;
        *(float4*)&out[(size_t)gm*DM_ + n0 + tx*4] = v;
    }
}

// ---------------- launch ----------------
extern "C" void kernel_launch(void* const* d_in, const int* in_sizes, int n_in,
                              void* d_out, int out_size) {
    const float* x    = (const float*)d_in[0];
    const int*   mask = (const int*)  d_in[1];
    const float* Wq = (const float*)d_in[2]; const float* bq = (const float*)d_in[3];
    const float* Wk = (const float*)d_in[4]; const float* bk = (const float*)d_in[5];
    const float* Wv = (const float*)d_in[6]; const float* bv = (const float*)d_in[7];
    const float* Wo = (const float*)d_in[8]; const float* bo = (const float*)d_in[9];
    float* out = (float*)d_out;

    mask_scan_kernel<<<BB, 256>>>(mask);
    cvt_w_kernel<<<dim3(8, 8, 3), dim3(32, 8)>>>(Wq, Wk, Wv);
    qkv_hmma_kernel<<<dim3(DM_/64, ROWS/64, 3), 128>>>(x, bq, bk, bv);
    vmean_kernel<<<BB*NH_, 256>>>();
    attn_mma_kernel<<<dim3(NN/64, BB*NH_), 128>>>();
    out_gemm_kernel<<<dim3(DM_/64, ROWS/64), 256>>>(Wo, bo, out);
}

// round 7
// speedup vs baseline: 5.5209x; 1.4234x over previous
#include <cuda_runtime.h>
#include <cuda_fp16.h>
#include <cstdint>

#define BB   8
#define NN   2048
#define DIN_ 256
#define DM_  256
#define NH_  4
#define DK_  64
#define ROWS (BB*NN)

// ---------------- scratch (no allocations allowed) ----------------
__device__ __half g_qb[BB*NH_*NN*DK_];   // pre-scaled by scale*log2(e)
__device__ __half g_kb[BB*NH_*NN*DK_];
__device__ __half g_vb[BB*NH_*NN*DK_];
__device__ __half g_wt[4*DM_*DIN_];      // W^T [z][n][k], fp16 (q,k,v,o)
__device__ __half g_att[ROWS*DM_];       // fp16 [b*n][h*64+d]
__device__ float g_vpart[BB*NH_*16*DK_];
__device__ float g_vmean[BB*NH_*DK_];
__device__ int   g_start[BB];
__device__ int   g_end[BB];              // exclusive bound = last-true index

#define SCL2E 0.18033688f   /* 0.125 * log2(e) */

// ---------------- small asm helpers ----------------
__device__ __forceinline__ uint32_t smem_u32(const void* p) {
    uint32_t a;
    asm("{ .reg .u64 t; cvta.to.shared.u64 t, %1; cvt.u32.u64 %0, t; }" : "=r"(a) : "l"(p));
    return a;
}
__device__ __forceinline__ float ex2f(float x) {
    float y; asm("ex2.approx.f32 %0, %1;" : "=f"(y) : "f"(x)); return y;
}
#define LDSM_X4(r0,r1,r2,r3,addr) \
    asm volatile("ldmatrix.sync.aligned.m8n8.x4.shared.b16 {%0,%1,%2,%3}, [%4];" \
        : "=r"(r0), "=r"(r1), "=r"(r2), "=r"(r3) : "r"(addr))
#define LDSM_X4_T(r0,r1,r2,r3,addr) \
    asm volatile("ldmatrix.sync.aligned.m8n8.x4.trans.shared.b16 {%0,%1,%2,%3}, [%4];" \
        : "=r"(r0), "=r"(r1), "=r"(r2), "=r"(r3) : "r"(addr))
#define MMA16816(c0,c1,c2,c3,a0,a1,a2,a3,b0,b1) \
    asm volatile("mma.sync.aligned.m16n8k16.row.col.f32.f16.f16.f32 " \
        "{%0,%1,%2,%3}, {%4,%5,%6,%7}, {%8,%9}, {%0,%1,%2,%3};" \
        : "+f"(c0), "+f"(c1), "+f"(c2), "+f"(c3) \
        : "r"(a0), "r"(a1), "r"(a2), "r"(a3), "r"(b0), "r"(b1))
#define CP_ASYNC16(smem, gptr) \
    asm volatile("cp.async.cg.shared.global [%0], [%1], 16;" :: "r"(smem), "l"(gptr))
#define CP_COMMIT() asm volatile("cp.async.commit_group;" ::: "memory")
#define CP_WAIT(n)  asm volatile("cp.async.wait_group %0;" :: "n"(n) : "memory")

// ---------------- mask scan ----------------
__global__ void mask_scan_kernel(const int* __restrict__ mask) {
    int b = blockIdx.x;
    __shared__ int smin, smax;
    if (threadIdx.x == 0) { smin = NN; smax = -1; }
    __syncthreads();
    int lmin = NN, lmax = -1;
    for (int i = threadIdx.x; i < NN; i += blockDim.x) {
        if (mask[b*NN + i]) { lmin = min(lmin, i); lmax = max(lmax, i); }
    }
    atomicMin(&smin, lmin);
    atomicMax(&smax, lmax);
    __syncthreads();
    if (threadIdx.x == 0) { g_start[b] = smin; g_end[b] = smax; }
}

// ---------------- weight transpose+convert: g_wt[z][n][k] = fp16(W[k][n]) ----------------
__global__ void cvt_w_kernel(const float* __restrict__ Wq, const float* __restrict__ Wk,
                             const float* __restrict__ Wv, const float* __restrict__ Wo) {
    __shared__ float t[32][33];
    const float* W = blockIdx.z == 0 ? Wq : blockIdx.z == 1 ? Wk :
                     blockIdx.z == 2 ? Wv : Wo;
    __half* wt = g_wt + (size_t)blockIdx.z * (DM_*DIN_);
    int n0 = blockIdx.x * 32, k0 = blockIdx.y * 32;
    for (int i = threadIdx.y; i < 32; i += 8)
        t[i][threadIdx.x] = W[(size_t)(k0 + i)*DM_ + n0 + threadIdx.x];
    __syncthreads();
    for (int i = threadIdx.y; i < 32; i += 8)
        wt[(size_t)(n0 + i)*DIN_ + k0 + threadIdx.x] = __float2half_rn(t[threadIdx.x][i]);
}

// ---------------- fused QKV GEMM, fp16 HMMA ----------------
#define GST 72
__global__ void __launch_bounds__(128) qkv_hmma_kernel(const float* __restrict__ x,
                                                       const float* __restrict__ bq,
                                                       const float* __restrict__ bk,
                                                       const float* __restrict__ bv)
{
    __shared__ __align__(16) __half sA[64*GST];
    __shared__ __align__(16) __half sB[64*GST];

    const int tid = threadIdx.x, lane = tid & 31, warp = tid >> 5;
    const int z = blockIdx.z;
    const int m0 = blockIdx.y * 64;
    const int h  = blockIdx.x;                 // 64-col tile == head
    const __half* wt = g_wt + (size_t)z * (DM_*DIN_);
    const float* bias = z == 0 ? bq : z == 1 ? bk : bv;
    __half* dst = z == 0 ? g_qb : z == 1 ? g_kb : g_vb;
    const float os = z == 0 ? SCL2E : 1.f;

    const uint32_t afb = smem_u32(sA) +
        (uint32_t)(((warp*16 + (lane & 15))*GST + (lane >> 4)*8) * 2);
    const uint32_t bfb = smem_u32(sB) +
        (uint32_t)(((((lane & 7) + ((lane >> 4) << 3))*GST) + ((lane >> 3) & 1)*8) * 2);

    float acc[32];
    #pragma unroll
    for (int i = 0; i < 32; i++) acc[i] = 0.f;

    for (int k0 = 0; k0 < DIN_; k0 += 64) {
        __syncthreads();
        for (int i = tid; i < 512; i += 128) {
            int r = i >> 3, j = i & 7;
            float4 a0 = *(const float4*)&x[(size_t)(m0 + r)*DIN_ + k0 + j*8];
            float4 a1 = *(const float4*)&x[(size_t)(m0 + r)*DIN_ + k0 + j*8 + 4];
            __half2 h0 = __float22half2_rn(make_float2(a0.x, a0.y));
            __half2 h1 = __float22half2_rn(make_float2(a0.z, a0.w));
            __half2 h2 = __float22half2_rn(make_float2(a1.x, a1.y));
            __half2 h3 = __float22half2_rn(make_float2(a1.z, a1.w));
            uint4 pk = make_uint4(*(uint32_t*)&h0, *(uint32_t*)&h1,
                                  *(uint32_t*)&h2, *(uint32_t*)&h3);
            *(uint4*)&sA[r*GST + j*8] = pk;
            *(uint4*)&sB[r*GST + j*8] = *(const uint4*)&wt[(size_t)(h*64 + r)*DIN_ + k0 + j*8];
        }
        __syncthreads();

        uint32_t af[4][4];
        #pragma unroll
        for (int ks = 0; ks < 4; ks++)
            LDSM_X4(af[ks][0], af[ks][1], af[ks][2], af[ks][3], afb + ks*32);

        #pragma unroll
        for (int ks = 0; ks < 4; ks++) {
            #pragma unroll
            for (int ntp = 0; ntp < 4; ntp++) {
                uint32_t b0, b1, b2, b3;
                LDSM_X4(b0, b1, b2, b3, bfb + (uint32_t)((ntp*16*GST + ks*16) * 2));
                MMA16816(acc[(2*ntp)*4+0], acc[(2*ntp)*4+1], acc[(2*ntp)*4+2], acc[(2*ntp)*4+3],
                         af[ks][0], af[ks][1], af[ks][2], af[ks][3], b0, b1);
                MMA16816(acc[(2*ntp+1)*4+0], acc[(2*ntp+1)*4+1], acc[(2*ntp+1)*4+2], acc[(2*ntp+1)*4+3],
                         af[ks][0], af[ks][1], af[ks][2], af[ks][3], b2, b3);
            }
        }
    }

    const int r_lo = m0 + warp*16 + (lane >> 2);
    const int r_hi = r_lo + 8;
    const int b_lo = r_lo >> 11, n_lo = r_lo & (NN - 1);
    const int b_hi = r_hi >> 11, n_hi = r_hi & (NN - 1);
    __half* p_lo = dst + ((((size_t)b_lo*NH_ + h)*NN) + n_lo)*DK_;
    __half* p_hi = dst + ((((size_t)b_hi*NH_ + h)*NN) + n_hi)*DK_;
    #pragma unroll
    for (int j = 0; j < 8; j++) {
        int d = j*8 + (lane & 3)*2;
        float2 bv2 = *(const float2*)&bias[h*64 + d];
        __half2 lo = __float22half2_rn(make_float2((acc[4*j+0] + bv2.x)*os,
                                                   (acc[4*j+1] + bv2.y)*os));
        __half2 hi = __float22half2_rn(make_float2((acc[4*j+2] + bv2.x)*os,
                                                   (acc[4*j+3] + bv2.y)*os));
        *(uint32_t*)&p_lo[d] = *(uint32_t*)&lo;
        *(uint32_t*)&p_hi[d] = *(uint32_t*)&hi;
    }
}

// ---------------- vmean: two-phase deterministic reduction ----------------
__global__ void vmean_part_kernel() {      // grid (32, 16), block 256
    __shared__ float red[256];
    int bh = blockIdx.x, seg = blockIdx.y;
    int d = threadIdx.x & 63, sub = threadIdx.x >> 6;
    const __half* vptr = g_vb + ((size_t)bh*NN + seg*128 + sub*32)*DK_;
    float s = 0.f;
    #pragma unroll 8
    for (int r = 0; r < 32; r++)
        s += __half2float(vptr[(size_t)r*DK_ + d]);
    red[threadIdx.x] = s;
    __syncthreads();
    if (sub == 0)
        g_vpart[((size_t)bh*16 + seg)*DK_ + d] =
            red[d] + red[64 + d] + red[128 + d] + red[192 + d];
}
__global__ void vmean_red_kernel() {       // grid 32, block 64
    int bh = blockIdx.x, d = threadIdx.x;
    float s = 0.f;
    #pragma unroll
    for (int i = 0; i < 16; i++)
        s += g_vpart[((size_t)bh*16 + i)*DK_ + d];
    g_vmean[bh*DK_ + d] = s * (1.f/NN);
}

// ---------------- HMMA fp16 flash attention + cp.async 2-stage pipeline ----------------
#define KST 72
#define STB ((uint32_t)(64*KST*2))

__device__ __forceinline__ void attn_prefetch(uint32_t skb, uint32_t svb,
                                              const __half* kp, const __half* vp,
                                              int kb, int tid) {
    #pragma unroll
    for (int u = 0; u < 4; u++) {
        int i = tid + u*128;
        int r = i >> 3, j = i & 7;
        int gr = kb + r; if (gr > NN - 1) gr = NN - 1;
        uint32_t so = (uint32_t)((r*KST + j*8) * 2);
        CP_ASYNC16(skb + so, kp + (size_t)gr*DK_ + j*8);
        CP_ASYNC16(svb + so, vp + (size_t)gr*DK_ + j*8);
    }
}

__global__ void __launch_bounds__(128) attn_mma_kernel() {
    __shared__ __align__(16) __half sQ[64*KST];
    __shared__ __align__(16) __half sK[2][64*KST];
    __shared__ __align__(16) __half sV[2][64*KST];

    const int tid = threadIdx.x, lane = tid & 31, warp = tid >> 5;
    const int bh = blockIdx.y, b = bh >> 2, h = bh & 3;
    const int q0 = blockIdx.x * 64;
    const int kstart = g_start[b], kend = g_end[b];
    __half* outbase = g_att + ((size_t)b*NN + q0)*DM_ + h*DK_;
    const float* vm = g_vmean + bh*DK_;

    const bool any = (q0 < kend) && (q0 + 63 >= kstart);
    if (!any) {   // whole tile invalid -> uniform softmax == mean(V)
        int r = tid >> 1, c0 = (tid & 1) * 32;
        #pragma unroll
        for (int j = 0; j < 8; j++) {
            __half2 a = __float22half2_rn(make_float2(vm[c0+j*4],   vm[c0+j*4+1]));
            __half2 c = __float22half2_rn(make_float2(vm[c0+j*4+2], vm[c0+j*4+3]));
            *(uint2*)&outbase[(size_t)r*DM_ + c0 + j*4] =
                make_uint2(*(uint32_t*)&a, *(uint32_t*)&c);
        }
        return;
    }

    const __half* qp = g_qb + ((size_t)bh*NN + q0)*DK_;
    const __half* kp = g_kb + (size_t)bh*NN*DK_;
    const __half* vp = g_vb + (size_t)bh*NN*DK_;

    const uint32_t skb0 = smem_u32(sK), svb0 = smem_u32(sV);
    const int kb0 = kstart & ~63;

    attn_prefetch(skb0, svb0, kp, vp, kb0, tid);
    CP_COMMIT();

    for (int i = tid; i < 512; i += 128) {
        int r = i >> 3, j = i & 7;
        *(uint4*)&sQ[r*KST + j*8] = *(const uint4*)&qp[r*DK_ + j*8];
    }
    __syncthreads();

    uint32_t qa[4][4];
    {
        uint32_t qaddr = smem_u32(sQ) + (uint32_t)(((warp*16 + (lane & 15))*KST + (lane >> 4)*8) * 2);
        #pragma unroll
        for (int ks = 0; ks < 4; ks++)
            LDSM_X4(qa[ks][0], qa[ks][1], qa[ks][2], qa[ks][3], qaddr + ks*32);
    }

    const uint32_t kfo = (uint32_t)(((((lane & 7) + ((lane >> 4) << 3))*KST) + ((lane >> 3) & 1)*8) * 2);
    const uint32_t vfo = (uint32_t)(((((lane & 7) + (((lane >> 3) & 1) << 3))*KST) + (lane >> 4)*8) * 2);

    float oacc[32];
    #pragma unroll
    for (int i = 0; i < 32; i++) oacc[i] = 0.f;
    float l_lo = 0.f, l_hi = 0.f;
    int st = 0;

    for (int kb = kb0; kb < kend; kb += 64) {
        const bool nxt = (kb + 64) < kend;
        if (nxt) {
            attn_prefetch(skb0 + (st^1)*STB, svb0 + (st^1)*STB, kp, vp, kb + 64, tid);
            CP_COMMIT();
            CP_WAIT(1);
        } else {
            CP_WAIT(0);
        }
        __syncthreads();

        const uint32_t kfbase = skb0 + st*STB + kfo;
        const uint32_t vfbase = svb0 + st*STB + vfo;

        float sacc[32];
        #pragma unroll
        for (int i = 0; i < 32; i++) sacc[i] = 0.f;
        #pragma unroll
        for (int ks = 0; ks < 4; ks++) {
            #pragma unroll
            for (int ntp = 0; ntp < 4; ntp++) {
                uint32_t b0, b1, b2, b3;
                LDSM_X4(b0, b1, b2, b3, kfbase + (uint32_t)((ntp*16*KST + ks*16) * 2));
                MMA16816(sacc[(2*ntp)*4+0], sacc[(2*ntp)*4+1], sacc[(2*ntp)*4+2], sacc[(2*ntp)*4+3],
                         qa[ks][0], qa[ks][1], qa[ks][2], qa[ks][3], b0, b1);
                MMA16816(sacc[(2*ntp+1)*4+0], sacc[(2*ntp+1)*4+1], sacc[(2*ntp+1)*4+2], sacc[(2*ntp+1)*4+3],
                         qa[ks][0], qa[ks][1], qa[ks][2], qa[ks][3], b2, b3);
            }
        }

        const bool partial = (kb < kstart) || (kb + 64 > kend);
        uint32_t ppack[16];
        float ls_lo = 0.f, ls_hi = 0.f;
        #pragma unroll
        for (int j = 0; j < 8; j++) {
            float c0 = sacc[4*j+0], c1 = sacc[4*j+1], c2 = sacc[4*j+2], c3 = sacc[4*j+3];
            float p0, p1, p2, p3;
            if (partial) {
                int col = kb + j*8 + (lane & 3)*2;
                bool v0 = (col >= kstart) & (col < kend);
                bool v1 = (col + 1 >= kstart) & (col + 1 < kend);
                p0 = v0 ? ex2f(c0) : 0.f;
                p1 = v1 ? ex2f(c1) : 0.f;
                p2 = v0 ? ex2f(c2) : 0.f;
                p3 = v1 ? ex2f(c3) : 0.f;
            } else {
                p0 = ex2f(c0); p1 = ex2f(c1); p2 = ex2f(c2); p3 = ex2f(c3);
            }
            __half2 q0p = __float22half2_rn(make_float2(p0, p1));
            __half2 q1p = __float22half2_rn(make_float2(p2, p3));
            ppack[2*j]   = *(uint32_t*)&q0p;
            ppack[2*j+1] = *(uint32_t*)&q1p;
            float2 f0 = __half22float2(q0p);
            float2 f1 = __half22float2(q1p);
            ls_lo += f0.x + f0.y;
            ls_hi += f1.x + f1.y;
        }
        ls_lo += __shfl_xor_sync(0xffffffffu, ls_lo, 1);
        ls_lo += __shfl_xor_sync(0xffffffffu, ls_lo, 2);
        ls_hi += __shfl_xor_sync(0xffffffffu, ls_hi, 1);
        ls_hi += __shfl_xor_sync(0xffffffffu, ls_hi, 2);
        l_lo += ls_lo;
        l_hi += ls_hi;

        #pragma unroll
        for (int kk = 0; kk < 4; kk++) {
            #pragma unroll
            for (int dt = 0; dt < 4; dt++) {
                uint32_t b0, b1, b2, b3;
                LDSM_X4_T(b0, b1, b2, b3, vfbase + (uint32_t)((kk*16*KST + dt*16) * 2));
                MMA16816(oacc[(2*dt)*4+0], oacc[(2*dt)*4+1], oacc[(2*dt)*4+2], oacc[(2*dt)*4+3],
                         ppack[4*kk+0], ppack[4*kk+1], ppack[4*kk+2], ppack[4*kk+3], b0, b1);
                MMA16816(oacc[(2*dt+1)*4+0], oacc[(2*dt+1)*4+1], oacc[(2*dt+1)*4+2], oacc[(2*dt+1)*4+3],
                         ppack[4*kk+0], ppack[4*kk+1], ppack[4*kk+2], ppack[4*kk+3], b2, b3);
            }
        }
        __syncthreads();
        st ^= 1;
    }

    // ---- epilogue (fp16 g_att) ----
    const int r_lo = q0 + warp*16 + (lane >> 2);
    const int r_hi = r_lo + 8;
    const bool v_lo = (r_lo >= kstart) && (r_lo < kend);
    const bool v_hi = (r_hi >= kstart) && (r_hi < kend);
    const float inv_lo = v_lo ? 1.f / l_lo : 0.f;
    const float inv_hi = v_hi ? 1.f / l_hi : 0.f;
    __half* orow_lo = g_att + ((size_t)b*NN + r_lo)*DM_ + h*DK_;
    __half* orow_hi = g_att + ((size_t)b*NN + r_hi)*DM_ + h*DK_;
    #pragma unroll
    for (int j = 0; j < 8; j++) {
        int d = j*8 + (lane & 3)*2;
        float2 lo, hi;
        if (v_lo) { lo.x = oacc[4*j+0]*inv_lo; lo.y = oacc[4*j+1]*inv_lo; }
        else      { lo.x = vm[d]; lo.y = vm[d+1]; }
        if (v_hi) { hi.x = oacc[4*j+2]*inv_hi; hi.y = oacc[4*j+3]*inv_hi; }
        else      { hi.x = vm[d]; hi.y = vm[d+1]; }
        __half2 lo2 = __float22half2_rn(lo);
        __half2 hi2 = __float22half2_rn(hi);
        *(uint32_t*)&orow_lo[d] = *(uint32_t*)&lo2;
        *(uint32_t*)&orow_hi[d] = *(uint32_t*)&hi2;
    }
}

// ---------------- output GEMM, fp16 HMMA: g_att [16384,256] x Wo + bo -> fp32 out ----------------
__global__ void __launch_bounds__(128) out_hmma_kernel(const float* __restrict__ bo,
                                                       float* __restrict__ out)
{
    __shared__ __align__(16) __half sA[64*GST];
    __shared__ __align__(16) __half sB[64*GST];

    const int tid = threadIdx.x, lane = tid & 31, warp = tid >> 5;
    const int m0 = blockIdx.y * 64;
    const int h  = blockIdx.x;                 // 64-col tile
    const __half* wt = g_wt + (size_t)3 * (DM_*DIN_);

    const uint32_t afb = smem_u32(sA) +
        (uint32_t)(((warp*16 + (lane & 15))*GST + (lane >> 4)*8) * 2);
    const uint32_t bfb = smem_u32(sB) +
        (uint32_t)(((((lane & 7) + ((lane >> 4) << 3))*GST) + ((lane >> 3) & 1)*8) * 2);

    float acc[32];
    #pragma unroll
    for (int i = 0; i < 32; i++) acc[i] = 0.f;

    for (int k0 = 0; k0 < DM_; k0 += 64) {
        __syncthreads();
        for (int i = tid; i < 512; i += 128) {
            int r = i >> 3, j = i & 7;
            *(uint4*)&sA[r*GST + j*8] = *(const uint4*)&g_att[(size_t)(m0 + r)*DM_ + k0 + j*8];
            *(uint4*)&sB[r*GST + j*8] = *(const uint4*)&wt[(size_t)(h*64 + r)*DIN_ + k0 + j*8];
        }
        __syncthreads();

        uint32_t af[4][4];
        #pragma unroll
        for (int ks = 0; ks < 4; ks++)
            LDSM_X4(af[ks][0], af[ks][1], af[ks][2], af[ks][3], afb + ks*32);

        #pragma unroll
        for (int ks = 0; ks < 4; ks++) {
            #pragma unroll
            for (int ntp = 0; ntp < 4; ntp++) {
                uint32_t b0, b1, b2, b3;
                LDSM_X4(b0, b1, b2, b3, bfb + (uint32_t)((ntp*16*GST + ks*16) * 2));
                MMA16816(acc[(2*ntp)*4+0], acc[(2*ntp)*4+1], acc[(2*ntp)*4+2], acc[(2*ntp)*4+3],
                         af[ks][0], af[ks][1], af[ks][2], af[ks][3], b0, b1);
                MMA16816(acc[(2*ntp+1)*4+0], acc[(2*ntp+1)*4+1], acc[(2*ntp+1)*4+2], acc[(2*ntp+1)*4+3],
                         af[ks][0], af[ks][1], af[ks][2], af[ks][3], b2, b3);
            }
        }
    }

    const int r_lo = m0 + warp*16 + (lane >> 2);
    const int r_hi = r_lo + 8;
    #pragma unroll
    for (int j = 0; j < 8; j++) {
        int d = j*8 + (lane & 3)*2;
        float2 bv2 = *(const float2*)&bo[h*64 + d];
        float2 lo = make_float2(acc[4*j+0] + bv2.x, acc[4*j+1] + bv2.y);
        float2 hi = make_float2(acc[4*j+2] + bv2.x, acc[4*j+3] + bv2.y);
        *(float2*)&out[(size_t)r_lo*DM_ + h*64 + d] = lo;
        *(float2*)&out[(size_t)r_hi*DM_ + h*64 + d] = hi;
    }
}

// ---------------- launch ----------------
extern "C" void kernel_launch(void* const* d_in, const int* in_sizes, int n_in,
                              void* d_out, int out_size) {
    const float* x    = (const float*)d_in[0];
    const int*   mask = (const int*)  d_in[1];
    const float* Wq = (const float*)d_in[2]; const float* bq = (const float*)d_in[3];
    const float* Wk = (const float*)d_in[4]; const float* bk = (const float*)d_in[5];
    const float* Wv = (const float*)d_in[6]; const float* bv = (const float*)d_in[7];
    const float* Wo = (const float*)d_in[8]; const float* bo = (const float*)d_in[9];
    float* out = (float*)d_out;

    mask_scan_kernel<<<BB, 256>>>(mask);
    cvt_w_kernel<<<dim3(8, 8, 4), dim3(32, 8)>>>(Wq, Wk, Wv, Wo);
    qkv_hmma_kernel<<<dim3(DM_/64, ROWS/64, 3), 128>>>(x, bq, bk, bv);
    vmean_part_kernel<<<dim3(BB*NH_, 16), 256>>>();
    vmean_red_kernel<<<BB*NH_, 64>>>();
    attn_mma_kernel<<<dim3(NN/64, BB*NH_), 128>>>();
    out_hmma_kernel<<<dim3(DM_/64, ROWS/64), 128>>>(bo, out);
}